// round 13
// baseline (speedup 1.0000x reference)
#include <cuda_runtime.h>
#include <cuda_fp16.h>
#include <math.h>

#define NUM_SPH 7
#define NUM_RAD 6
#define NBASIS  (NUM_SPH * NUM_RAD)   // 42
#define MAX_E   524288

#define TABN    512                   // lerp intervals over x in [0.1, 1.0]
#define NREC    (NBASIS / 2)          // 21 packed records per row

#define BT      128                   // triplets per out-block
#define OTPB    224                   // 7 warps; 128*42/4 = 1344 = 6*224
#define NCHUNK  4

// root scan grid: x in [3.0, 34.035]
#define SCAN_NP   6208
#define SCAN_LO   3.0
#define SCAN_H    0.005

// --------------------------------------------------------------------------
__device__ float g_zeros[NUM_SPH][NUM_RAD];
__device__ float g_norms[NUM_SPH][NUM_RAD];
// packed record per (row i, even j): half4 = (v_j, v_j+1, d_j, d_j+1), 8B.
// row stride = 21 records = 168B. total = 513*168B = 86KB -> L1-resident.
__device__ __align__(256) uint2 g_tabp[(size_t)(TABN + 1) * NREC];

// --------------------------------------------------------------------------
__device__ __forceinline__ void jn_pair_d(int l, double z, double& f, double& fm) {
    double s = sin(z), c = cos(z);
    double j0 = s / z;
    if (l == 0) { f = j0; fm = c / z; return; }      // j_{-1} = cos/z
    double j1 = s / (z * z) - c / z;
    double a = j0, b = j1;
    for (int i = 1; i < l; ++i) {
        double nx = (2.0 * i + 1.0) / z * b - a;
        a = b; b = nx;
    }
    f = b; fm = a;
}

// --------------------------------------------------------------------------
// 1) fused scan + bracket + Newton: one block per l.
// --------------------------------------------------------------------------
__global__ void setup_kernel() {
    __shared__ unsigned char sg[SCAN_NP];
    __shared__ int cnt[256];
    __shared__ int brk[NUM_RAD];
    int l = blockIdx.x;
    int t = threadIdx.x;

    for (int p = t; p < SCAN_NP; p += 256) {
        float x = (float)(SCAN_LO + SCAN_H * (double)p);
        float s, c;
        sincosf(x, &s, &c);
        float j0 = s / x;
        float v = j0;
        if (l > 0) {
            float j1 = s / (x * x) - c / x;
            float a = j0, b = j1;
            for (int i = 1; i < l; ++i) {
                float nx = (2.0f * i + 1.0f) / x * b - a;
                a = b; b = nx;
            }
            v = b;
        }
        sg[p] = (unsigned char)(v < 0.0f);
    }
    __syncthreads();

    const int NI  = SCAN_NP - 1;
    const int per = (NI + 255) / 256;
    int i0 = t * per, i1 = i0 + per; if (i1 > NI) i1 = NI;

    int local = 0;
    for (int i = i0; i < i1; ++i) local += (sg[i] != sg[i + 1]);
    cnt[t] = local;
    __syncthreads();

    if (t == 0) {
        int run = 0;
        for (int j = 0; j < 256; ++j) { int c0 = cnt[j]; cnt[j] = run; run += c0; }
    }
    __syncthreads();

    int r = cnt[t];
    for (int i = i0; i < i1; ++i) {
        if (sg[i] != sg[i + 1]) {
            if (r < NUM_RAD) brk[r] = i;
            ++r;
        }
    }
    __syncthreads();

    if (t < NUM_RAD) {
        int k = t;
        int i = brk[k];
        double lo = SCAN_LO + SCAN_H * (double)i - SCAN_H;
        double hi = lo + 3.0 * SCAN_H;
        double flo, fd;
        jn_pair_d(l, lo, flo, fd);

        double z = 0.5 * (lo + hi);
        for (int it = 0; it < 5; ++it) {
            double f, fm;
            jn_pair_d(l, z, f, fm);
            if ((f < 0.0) == (flo < 0.0)) { lo = z; flo = f; } else { hi = z; }
            double fp = fm - ((double)(l + 1) / z) * f;
            double zn = z - f / fp;
            if (!(zn > lo && zn < hi)) zn = 0.5 * (lo + hi);
            z = zn;
        }

        double f7, fm7;
        jn_pair_d(l + 1, z, f7, fm7);
        g_zeros[l][k] = (float)z;
        g_norms[l][k] = (float)(sqrt(2.0) / fabs(f7));
    }
}

// --------------------------------------------------------------------------
// helper: fp32 reference recurrence, 6 radial values for (x, l)
// --------------------------------------------------------------------------
__device__ __forceinline__ void rbf_row(float x, int l, float* outv) {
    #pragma unroll
    for (int k = 0; k < NUM_RAD; ++k) {
        float z = x * g_zeros[l][k];
        float s, c;
        sincosf(z, &s, &c);
        float j0 = s / z;
        float res = j0;
        if (l > 0) {
            float j1 = s / (z * z) - c / z;
            float jm = j0, jc = j1;
            for (int i = 1; i < l; ++i) {
                float jn = (2.0f * i + 1.0f) / z * jc - jm;
                jm = jc; jc = jn;
            }
            res = jc;
        }
        outv[k] = g_norms[l][k] * res;
    }
}

// --------------------------------------------------------------------------
// 2) Table-gen: per (grid point p, l) thread computes rbf at x_p and x_{p+1},
//    packs (v, d=v'-v) as half4 records directly.
// --------------------------------------------------------------------------
__global__ void tab_kernel() {
    int gid = blockIdx.x * blockDim.x + threadIdx.x;
    if (gid >= (TABN + 1) * NUM_SPH) return;
    int l = gid % NUM_SPH;
    int p = gid / NUM_SPH;
    float x0 = 0.1f + (0.9f / TABN) * (float)p;
    float x1 = 0.1f + (0.9f / TABN) * (float)(p + 1);   // d unused for p==TABN

    float v0[NUM_RAD], v1[NUM_RAD];
    rbf_row(x0, l, v0);
    rbf_row(x1, l, v1);

    uint2* row = g_tabp + (size_t)p * NREC + l * (NUM_RAD / 2);
    #pragma unroll
    for (int r = 0; r < NUM_RAD / 2; ++r) {
        __half2 vh = __floats2half2_rn(v0[2*r], v0[2*r+1]);
        __half2 dh = __floats2half2_rn(v1[2*r] - v0[2*r], v1[2*r+1] - v0[2*r+1]);
        uint2 rec;
        rec.x = *reinterpret_cast<unsigned*>(&vh);
        rec.y = *reinterpret_cast<unsigned*>(&dh);
        row[r] = rec;
    }
}

// --------------------------------------------------------------------------
// 3) FUSED out, float4-granularity: per float4 output = 2 scattered LDG.64
//    (packed half4 records, L1-resident 86KB table) + LDS + 1 dense STG.128.
//    The (tl2, j2) pair handles the j==40 triplet straddle.
// --------------------------------------------------------------------------
__global__ void __launch_bounds__(OTPB) out_kernel(
        const float* __restrict__ dist,
        const float* __restrict__ angle,
        const int*   __restrict__ idx_kj,
        float*       __restrict__ out,
        int blockOff) {
    __shared__ float scbf[BT][8];
    __shared__ float2 sif[BT];          // (row record-offset as int bits, lerp f)

    const float pref[NUM_SPH] = {
        0.28209479177387814f, 0.48860251190291992f, 0.63078313050504009f,
        0.74635266518023080f, 0.84628437532163443f, 0.93560257962738880f,
        1.01710723628205460f
    };

    int blk = blockIdx.x + blockOff;
    int tid = threadIdx.x;
    int t0  = blk * BT;

    // ---- 1a ----
    if (tid < BT) {
        int t = t0 + tid;
        int e = __ldg(&idx_kj[t]);
        float x = __ldg(&dist[e]) * 0.2f;
        float u = (x - 0.1f) * ((float)TABN / 0.9f);
        if (u < 0.0f) u = 0.0f;
        int i = (int)u;
        if (i > TABN - 1) i = TABN - 1;
        sif[tid] = make_float2(__int_as_float(i * NREC), u - (float)i);

        float ct = cosf(angle[t]);
        float pm = 1.0f, pc = ct;
        scbf[tid][0] = pref[0] * pm;
        scbf[tid][1] = pref[1] * pc;
        #pragma unroll
        for (int l = 2; l < NUM_SPH; ++l) {
            float pn = ((2.0f * l - 1.0f) * ct * pc - (l - 1.0f) * pm) / (float)l;
            pm = pc; pc = pn;
            scbf[tid][l] = pref[l] * pn;
        }
    }
    __syncthreads();

    // ---- 2 ----
    float4* o4 = reinterpret_cast<float4*>(out + (size_t)blk * (BT * NBASIS));

    #pragma unroll
    for (int it = 0; it < 6; ++it) {
        unsigned w  = it * OTPB + tid;          // 0..1343
        unsigned g  = 4u * w;
        unsigned tl = (g * 6242u) >> 18;        // g/42, exact for g<5376
        unsigned j  = g - tl * 42u;             // even, 0..40

        unsigned tl2 = tl, j2 = j + 2u;
        if (j2 == 42u) { j2 = 0u; tl2 = tl + 1u; }

        float2 rf1 = sif[tl];
        float2 rf2 = sif[tl2];
        int    ro1 = __float_as_int(rf1.x);     // i1 * NREC
        int    ro2 = __float_as_int(rf2.x);
        float  f1  = rf1.y;
        float  f2  = rf2.y;

        uint2 rc1 = __ldg(&g_tabp[ro1 + (j  >> 1)]);
        uint2 rc2 = __ldg(&g_tabp[ro2 + (j2 >> 1)]);
        float2 v1 = __half22float2(*reinterpret_cast<__half2*>(&rc1.x));
        float2 d1 = __half22float2(*reinterpret_cast<__half2*>(&rc1.y));
        float2 v2 = __half22float2(*reinterpret_cast<__half2*>(&rc2.x));
        float2 d2 = __half22float2(*reinterpret_cast<__half2*>(&rc2.y));

        float c1 = scbf[tl ][(j  * 171u) >> 10];   // j/6
        float c2 = scbf[tl2][(j2 * 171u) >> 10];

        float4 r;
        r.x = (v1.x + f1 * d1.x) * c1;
        r.y = (v1.y + f1 * d1.y) * c1;
        r.z = (v2.x + f2 * d2.x) * c2;
        r.w = (v2.y + f2 * d2.y) * c2;
        __stcs(&o4[w], r);
    }
}

// --------------------------------------------------------------------------
extern "C" void kernel_launch(void* const* d_in, const int* in_sizes, int n_in,
                              void* d_out, int out_size) {
    const float* dist  = (const float*)d_in[0];
    const float* angle = (const float*)d_in[1];
    const int*   idx   = (const int*)  d_in[2];
    float*       out   = (float*)      d_out;
    int T = in_sizes[1];

    setup_kernel<<<NUM_SPH, 256>>>();

    int nTab = (TABN + 1) * NUM_SPH;
    tab_kernel<<<(nTab + 255) / 256, 256>>>();

    int nBlk  = T / BT;                       // 32768
    int chunk = (nBlk + NCHUNK - 1) / NCHUNK; // 8192
    for (int c = 0; c < NCHUNK; ++c) {
        int off = c * chunk;
        int nb  = (off + chunk <= nBlk) ? chunk : (nBlk - off);
        if (nb > 0) out_kernel<<<nb, OTPB>>>(dist, angle, idx, out, off);
    }
}

// round 14
// speedup vs baseline: 1.0550x; 1.0550x over previous
#include <cuda_runtime.h>
#include <cuda_fp16.h>
#include <math.h>

#define NUM_SPH 7
#define NUM_RAD 6
#define NBASIS  (NUM_SPH * NUM_RAD)   // 42
#define MAX_E   524288

#define TABN    512                   // lerp intervals over x in [0.1, 1.0]
#define NREC    (NBASIS / 2)          // 21 packed records per row

#define BT      128                   // triplets per out-block
#define OTPB    224                   // 7 warps; 128*42/2 = 2688 = 12*224
#define NCHUNK  2

// root scan grid: x in [3.0, 34.035]
#define SCAN_NP   6208
#define SCAN_LO   3.0
#define SCAN_H    0.005

// --------------------------------------------------------------------------
// packed record per (row i, even j): half4 = (v_j, v_j+1, d_j, d_j+1), 8B.
// row stride = 21 records = 168B. total = 513*168B = 86KB -> L1-resident.
__device__ __align__(256) uint2 g_tabp[(size_t)(TABN + 1) * NREC];

// --------------------------------------------------------------------------
__device__ __forceinline__ void jn_pair_d(int l, double z, double& f, double& fm) {
    double s = sin(z), c = cos(z);
    double j0 = s / z;
    if (l == 0) { f = j0; fm = c / z; return; }      // j_{-1} = cos/z
    double j1 = s / (z * z) - c / z;
    double a = j0, b = j1;
    for (int i = 1; i < l; ++i) {
        double nx = (2.0 * i + 1.0) / z * b - a;
        a = b; b = nx;
    }
    f = b; fm = a;
}

// --------------------------------------------------------------------------
// FUSED setup+tab: one block per l.
//  A: fp32 sign-scan of j_l on the root grid (SMEM)
//  B: bracket count -> threads 0..5 run safeguarded fp64 Newton -> zeros/norms
//  C: evaluate fp32 reference recurrence at 513 table points (SMEM stage)
//  D: pack (v, d) half4 records into this l's slice of g_tabp
// --------------------------------------------------------------------------
__global__ void setup_tab_kernel() {
    __shared__ unsigned char sg[SCAN_NP];
    __shared__ int cnt[256];
    __shared__ int brk[NUM_RAD];
    __shared__ float szeros[NUM_RAD];
    __shared__ float snorms[NUM_RAD];
    __shared__ float sval[TABN + 1][NUM_RAD];   // 12.3 KB
    int l = blockIdx.x;
    int t = threadIdx.x;

    // ---- A: sign scan ----
    for (int p = t; p < SCAN_NP; p += 256) {
        float x = (float)(SCAN_LO + SCAN_H * (double)p);
        float s, c;
        sincosf(x, &s, &c);
        float j0 = s / x;
        float v = j0;
        if (l > 0) {
            float j1 = s / (x * x) - c / x;
            float a = j0, b = j1;
            for (int i = 1; i < l; ++i) {
                float nx = (2.0f * i + 1.0f) / x * b - a;
                a = b; b = nx;
            }
            v = b;
        }
        sg[p] = (unsigned char)(v < 0.0f);
    }
    __syncthreads();

    // ---- B: brackets + Newton ----
    const int NI  = SCAN_NP - 1;
    const int per = (NI + 255) / 256;
    int i0 = t * per, i1 = i0 + per; if (i1 > NI) i1 = NI;

    int local = 0;
    for (int i = i0; i < i1; ++i) local += (sg[i] != sg[i + 1]);
    cnt[t] = local;
    __syncthreads();

    if (t == 0) {
        int run = 0;
        for (int j = 0; j < 256; ++j) { int c0 = cnt[j]; cnt[j] = run; run += c0; }
    }
    __syncthreads();

    int r = cnt[t];
    for (int i = i0; i < i1; ++i) {
        if (sg[i] != sg[i + 1]) {
            if (r < NUM_RAD) brk[r] = i;
            ++r;
        }
    }
    __syncthreads();

    if (t < NUM_RAD) {
        int k = t;
        int i = brk[k];
        double lo = SCAN_LO + SCAN_H * (double)i - SCAN_H;
        double hi = lo + 3.0 * SCAN_H;
        double flo, fd;
        jn_pair_d(l, lo, flo, fd);

        double z = 0.5 * (lo + hi);
        for (int it = 0; it < 5; ++it) {
            double f, fm;
            jn_pair_d(l, z, f, fm);
            if ((f < 0.0) == (flo < 0.0)) { lo = z; flo = f; } else { hi = z; }
            double fp = fm - ((double)(l + 1) / z) * f;
            double zn = z - f / fp;
            if (!(zn > lo && zn < hi)) zn = 0.5 * (lo + hi);
            z = zn;
        }

        double f7, fm7;
        jn_pair_d(l + 1, z, f7, fm7);
        szeros[k] = (float)z;
        snorms[k] = (float)(sqrt(2.0) / fabs(f7));
    }
    __syncthreads();

    // ---- C: table values (each grid point's sincosf computed once) ----
    for (int p = t; p <= TABN; p += 256) {
        float x = 0.1f + (0.9f / TABN) * (float)p;
        #pragma unroll
        for (int k = 0; k < NUM_RAD; ++k) {
            float z = x * szeros[k];
            float s, c;
            sincosf(z, &s, &c);
            float j0 = s / z;
            float res = j0;
            if (l > 0) {
                float j1 = s / (z * z) - c / z;
                float jm = j0, jc = j1;
                for (int i = 1; i < l; ++i) {
                    float jn = (2.0f * i + 1.0f) / z * jc - jm;
                    jm = jc; jc = jn;
                }
                res = jc;
            }
            sval[p][k] = snorms[k] * res;
        }
    }
    __syncthreads();

    // ---- D: pack records ----
    for (int p = t; p < TABN; p += 256) {
        uint2* row = g_tabp + (size_t)p * NREC + l * (NUM_RAD / 2);
        #pragma unroll
        for (int r2 = 0; r2 < NUM_RAD / 2; ++r2) {
            float a0 = sval[p][2*r2],     a1 = sval[p][2*r2+1];
            float b0 = sval[p+1][2*r2],   b1 = sval[p+1][2*r2+1];
            __half2 vh = __floats2half2_rn(a0, a1);
            __half2 dh = __floats2half2_rn(b0 - a0, b1 - a1);
            uint2 rec;
            rec.x = *reinterpret_cast<unsigned*>(&vh);
            rec.y = *reinterpret_cast<unsigned*>(&dh);
            row[r2] = rec;
        }
    }
    // row TABN: only v needed (clamped i <= TABN-1 in out_kernel), but fill
    // it anyway for safety (d = 0).
    if (t < NUM_RAD / 2) {
        uint2* row = g_tabp + (size_t)TABN * NREC + l * (NUM_RAD / 2);
        float a0 = sval[TABN][2*t], a1 = sval[TABN][2*t+1];
        __half2 vh = __floats2half2_rn(a0, a1);
        __half2 dh = __floats2half2_rn(0.0f, 0.0f);
        uint2 rec;
        rec.x = *reinterpret_cast<unsigned*>(&vh);
        rec.y = *reinterpret_cast<unsigned*>(&dh);
        row[t] = rec;
    }
}

// --------------------------------------------------------------------------
// FUSED out (R12 float2 version): per float2 output = 1 scattered LDG.64
// (packed half4 record, L1-resident 86KB table) + LDS + dense STG.64.
// --------------------------------------------------------------------------
__global__ void __launch_bounds__(OTPB) out_kernel(
        const float* __restrict__ dist,
        const float* __restrict__ angle,
        const int*   __restrict__ idx_kj,
        float*       __restrict__ out,
        int blockOff) {
    __shared__ float scbf[BT][8];
    __shared__ float2 sif[BT];          // (row record-offset as int bits, lerp f)

    const float pref[NUM_SPH] = {
        0.28209479177387814f, 0.48860251190291992f, 0.63078313050504009f,
        0.74635266518023080f, 0.84628437532163443f, 0.93560257962738880f,
        1.01710723628205460f
    };

    int blk = blockIdx.x + blockOff;
    int tid = threadIdx.x;
    int t0  = blk * BT;

    // ---- 1a ----
    if (tid < BT) {
        int t = t0 + tid;
        int e = __ldg(&idx_kj[t]);
        float x = __ldg(&dist[e]) * 0.2f;
        float u = (x - 0.1f) * ((float)TABN / 0.9f);
        if (u < 0.0f) u = 0.0f;
        int i = (int)u;
        if (i > TABN - 1) i = TABN - 1;
        sif[tid] = make_float2(__int_as_float(i * NREC), u - (float)i);

        float ct = cosf(angle[t]);
        float pm = 1.0f, pc = ct;
        scbf[tid][0] = pref[0] * pm;
        scbf[tid][1] = pref[1] * pc;
        #pragma unroll
        for (int l = 2; l < NUM_SPH; ++l) {
            float pn = ((2.0f * l - 1.0f) * ct * pc - (l - 1.0f) * pm) / (float)l;
            pm = pc; pc = pn;
            scbf[tid][l] = pref[l] * pn;
        }
    }
    __syncthreads();

    // ---- 2 ----
    float2* o2 = reinterpret_cast<float2*>(out + (size_t)blk * (BT * NBASIS));

    #pragma unroll
    for (int it = 0; it < 12; ++it) {
        unsigned w  = it * OTPB + tid;          // 0..2687
        unsigned g  = 2u * w;                   // even
        unsigned tl = (g * 6242u) >> 18;        // g/42, exact for g<5376
        unsigned j  = g - tl * 42u;             // even, 0..40
        unsigned rj = j >> 1;                   // record index within row

        float2 rf = sif[tl];
        int    ro = __float_as_int(rf.x);       // i * NREC
        float  f  = rf.y;

        uint2 rec = __ldg(&g_tabp[ro + rj]);
        float2 v = __half22float2(*reinterpret_cast<__half2*>(&rec.x));
        float2 d = __half22float2(*reinterpret_cast<__half2*>(&rec.y));

        float c = scbf[tl][(j * 171u) >> 10];   // j/6

        float2 r;
        r.x = (v.x + f * d.x) * c;
        r.y = (v.y + f * d.y) * c;
        __stcs(&o2[w], r);
    }
}

// --------------------------------------------------------------------------
extern "C" void kernel_launch(void* const* d_in, const int* in_sizes, int n_in,
                              void* d_out, int out_size) {
    const float* dist  = (const float*)d_in[0];
    const float* angle = (const float*)d_in[1];
    const int*   idx   = (const int*)  d_in[2];
    float*       out   = (float*)      d_out;
    int T = in_sizes[1];

    setup_tab_kernel<<<NUM_SPH, 256>>>();

    int nBlk  = T / BT;                       // 32768
    int chunk = (nBlk + NCHUNK - 1) / NCHUNK; // 16384
    for (int c = 0; c < NCHUNK; ++c) {
        int off = c * chunk;
        int nb  = (off + chunk <= nBlk) ? chunk : (nBlk - off);
        if (nb > 0) out_kernel<<<nb, OTPB>>>(dist, angle, idx, out, off);
    }
}

// round 15
// speedup vs baseline: 1.2732x; 1.2068x over previous
#include <cuda_runtime.h>
#include <cuda_fp16.h>
#include <math.h>

#define NUM_SPH 7
#define NUM_RAD 6
#define NBASIS  (NUM_SPH * NUM_RAD)   // 42
#define MAX_E   524288

#define TABN    512                   // lerp intervals over x in [0.1, 1.0]
#define NREC    (NBASIS / 2)          // 21 packed records per row

#define BT      128                   // triplets per out-block
#define OTPB    224                   // 7 warps; 128*42/2 = 2688 = 12*224
#define NCHUNK  2

// root scan grid: x in [3.0, 3.0 + 0.02*1551 = 34.02]
#define SCAN_NP   1552
#define SCAN_LO   3.0f
#define SCAN_H    0.02f

// --------------------------------------------------------------------------
// packed record per (row i, even j): half4 = (v_j, v_j+1, d_j, d_j+1), 8B.
// row stride = 21 records = 168B. total = 513*168B = 86KB -> L1-resident.
__device__ __align__(256) uint2 g_tabp[(size_t)(TABN + 1) * NREC];

// --------------------------------------------------------------------------
// spherical Bessel pair (j_l, j_{l-1}): fp64 (polish/norm) and fp32 (Newton)
// --------------------------------------------------------------------------
__device__ __forceinline__ void jn_pair_d(int l, double z, double& f, double& fm) {
    double s = sin(z), c = cos(z);
    double j0 = s / z;
    if (l == 0) { f = j0; fm = c / z; return; }      // j_{-1} = cos/z
    double j1 = s / (z * z) - c / z;
    double a = j0, b = j1;
    for (int i = 1; i < l; ++i) {
        double nx = (2.0 * i + 1.0) / z * b - a;
        a = b; b = nx;
    }
    f = b; fm = a;
}

__device__ __forceinline__ void jn_pair_f(int l, float z, float& f, float& fm) {
    float s, c;
    sincosf(z, &s, &c);
    float j0 = s / z;
    if (l == 0) { f = j0; fm = c / z; return; }
    float j1 = s / (z * z) - c / z;
    float a = j0, b = j1;
    for (int i = 1; i < l; ++i) {
        float nx = (2.0f * i + 1.0f) / z * b - a;
        a = b; b = nx;
    }
    f = b; fm = a;
}

// --------------------------------------------------------------------------
// FUSED setup+tab: one block per l.
//  A: fp32 sign-scan of j_l on the root grid (SMEM)
//  B: brackets -> threads 0..5: fp32 Newton (4 it) + 1 fp64 polish -> zeros/norms
//  C: fp32 reference recurrence at 513 table points (SMEM stage)
//  D: pack (v, d) half4 records into this l's slice of g_tabp
// --------------------------------------------------------------------------
__global__ void setup_tab_kernel() {
    __shared__ unsigned char sg[SCAN_NP];
    __shared__ int cnt[256];
    __shared__ int brk[NUM_RAD];
    __shared__ float szeros[NUM_RAD];
    __shared__ float snorms[NUM_RAD];
    __shared__ float sval[TABN + 1][NUM_RAD];   // 12.3 KB
    int l = blockIdx.x;
    int t = threadIdx.x;

    // ---- A: sign scan ----
    for (int p = t; p < SCAN_NP; p += 256) {
        float x = SCAN_LO + SCAN_H * (float)p;
        float v, vm;
        jn_pair_f(l, x, v, vm);
        sg[p] = (unsigned char)(v < 0.0f);
    }
    __syncthreads();

    // ---- B: brackets + Newton ----
    const int NI  = SCAN_NP - 1;
    const int per = (NI + 255) / 256;
    int i0 = t * per, i1 = i0 + per; if (i1 > NI) i1 = NI;

    int local = 0;
    for (int i = i0; i < i1; ++i) local += (sg[i] != sg[i + 1]);
    cnt[t] = local;
    __syncthreads();

    if (t == 0) {
        int run = 0;
        for (int j = 0; j < 256; ++j) { int c0 = cnt[j]; cnt[j] = run; run += c0; }
    }
    __syncthreads();

    int r = cnt[t];
    for (int i = i0; i < i1; ++i) {
        if (sg[i] != sg[i + 1]) {
            if (r < NUM_RAD) brk[r] = i;
            ++r;
        }
    }
    __syncthreads();

    if (t < NUM_RAD) {
        int k = t;
        int i = brk[k];
        // expanded bracket (fp32 sign slop at grid ends)
        float lo = SCAN_LO + SCAN_H * (float)i - SCAN_H;
        float hi = lo + 3.0f * SCAN_H;
        float flo, fd;
        jn_pair_f(l, lo, flo, fd);

        // 4 safeguarded fp32 Newton iterations -> ~1e-6
        float z = 0.5f * (lo + hi);
        #pragma unroll
        for (int it = 0; it < 4; ++it) {
            float f, fm;
            jn_pair_f(l, z, f, fm);
            if ((f < 0.0f) == (flo < 0.0f)) { lo = z; flo = f; } else { hi = z; }
            float fp = fm - ((float)(l + 1) / z) * f;
            float zn = z - f / fp;
            if (!(zn > lo && zn < hi)) zn = 0.5f * (lo + hi);
            z = zn;
        }

        // single fp64 Newton polish -> ~1e-12
        double zd = (double)z;
        {
            double f, fm;
            jn_pair_d(l, zd, f, fm);
            double fp = fm - ((double)(l + 1) / zd) * f;
            zd = zd - f / fp;
        }

        double f7, fm7;
        jn_pair_d(l + 1, zd, f7, fm7);
        szeros[k] = (float)zd;
        snorms[k] = (float)(sqrt(2.0) / fabs(f7));
    }
    __syncthreads();

    // ---- C: table values (each grid point's sincosf computed once) ----
    for (int p = t; p <= TABN; p += 256) {
        float x = 0.1f + (0.9f / TABN) * (float)p;
        #pragma unroll
        for (int k = 0; k < NUM_RAD; ++k) {
            float z = x * szeros[k];
            float s, c;
            sincosf(z, &s, &c);
            float j0 = s / z;
            float res = j0;
            if (l > 0) {
                float j1 = s / (z * z) - c / z;
                float jm = j0, jc = j1;
                for (int i = 1; i < l; ++i) {
                    float jn = (2.0f * i + 1.0f) / z * jc - jm;
                    jm = jc; jc = jn;
                }
                res = jc;
            }
            sval[p][k] = snorms[k] * res;
        }
    }
    __syncthreads();

    // ---- D: pack records ----
    for (int p = t; p < TABN; p += 256) {
        uint2* row = g_tabp + (size_t)p * NREC + l * (NUM_RAD / 2);
        #pragma unroll
        for (int r2 = 0; r2 < NUM_RAD / 2; ++r2) {
            float a0 = sval[p][2*r2],     a1 = sval[p][2*r2+1];
            float b0 = sval[p+1][2*r2],   b1 = sval[p+1][2*r2+1];
            __half2 vh = __floats2half2_rn(a0, a1);
            __half2 dh = __floats2half2_rn(b0 - a0, b1 - a1);
            uint2 rec;
            rec.x = *reinterpret_cast<unsigned*>(&vh);
            rec.y = *reinterpret_cast<unsigned*>(&dh);
            row[r2] = rec;
        }
    }
    if (t < NUM_RAD / 2) {     // row TABN (v only; d = 0)
        uint2* row = g_tabp + (size_t)TABN * NREC + l * (NUM_RAD / 2);
        float a0 = sval[TABN][2*t], a1 = sval[TABN][2*t+1];
        __half2 vh = __floats2half2_rn(a0, a1);
        __half2 dh = __floats2half2_rn(0.0f, 0.0f);
        uint2 rec;
        rec.x = *reinterpret_cast<unsigned*>(&vh);
        rec.y = *reinterpret_cast<unsigned*>(&dh);
        row[t] = rec;
    }
}

// --------------------------------------------------------------------------
// FUSED out (R12 float2 version — best measured): per float2 output =
// 1 scattered LDG.64 (packed half4 record, L1-resident 86KB table) + LDS +
// dense STG.64 (evict-first).
// --------------------------------------------------------------------------
__global__ void __launch_bounds__(OTPB) out_kernel(
        const float* __restrict__ dist,
        const float* __restrict__ angle,
        const int*   __restrict__ idx_kj,
        float*       __restrict__ out,
        int blockOff) {
    __shared__ float scbf[BT][8];
    __shared__ float2 sif[BT];          // (row record-offset as int bits, lerp f)

    const float pref[NUM_SPH] = {
        0.28209479177387814f, 0.48860251190291992f, 0.63078313050504009f,
        0.74635266518023080f, 0.84628437532163443f, 0.93560257962738880f,
        1.01710723628205460f
    };

    int blk = blockIdx.x + blockOff;
    int tid = threadIdx.x;
    int t0  = blk * BT;

    // ---- 1a ----
    if (tid < BT) {
        int t = t0 + tid;
        int e = __ldg(&idx_kj[t]);
        float x = __ldg(&dist[e]) * 0.2f;
        float u = (x - 0.1f) * ((float)TABN / 0.9f);
        if (u < 0.0f) u = 0.0f;
        int i = (int)u;
        if (i > TABN - 1) i = TABN - 1;
        sif[tid] = make_float2(__int_as_float(i * NREC), u - (float)i);

        float ct = cosf(angle[t]);
        float pm = 1.0f, pc = ct;
        scbf[tid][0] = pref[0] * pm;
        scbf[tid][1] = pref[1] * pc;
        #pragma unroll
        for (int l = 2; l < NUM_SPH; ++l) {
            float pn = ((2.0f * l - 1.0f) * ct * pc - (l - 1.0f) * pm) / (float)l;
            pm = pc; pc = pn;
            scbf[tid][l] = pref[l] * pn;
        }
    }
    __syncthreads();

    // ---- 2 ----
    float2* o2 = reinterpret_cast<float2*>(out + (size_t)blk * (BT * NBASIS));

    #pragma unroll
    for (int it = 0; it < 12; ++it) {
        unsigned w  = it * OTPB + tid;          // 0..2687
        unsigned g  = 2u * w;                   // even
        unsigned tl = (g * 6242u) >> 18;        // g/42, exact for g<5376
        unsigned j  = g - tl * 42u;             // even, 0..40
        unsigned rj = j >> 1;                   // record index within row

        float2 rf = sif[tl];
        int    ro = __float_as_int(rf.x);       // i * NREC
        float  f  = rf.y;

        uint2 rec = __ldg(&g_tabp[ro + rj]);
        float2 v = __half22float2(*reinterpret_cast<__half2*>(&rec.x));
        float2 d = __half22float2(*reinterpret_cast<__half2*>(&rec.y));

        float c = scbf[tl][(j * 171u) >> 10];   // j/6

        float2 r;
        r.x = (v.x + f * d.x) * c;
        r.y = (v.y + f * d.y) * c;
        __stcs(&o2[w], r);
    }
}

// --------------------------------------------------------------------------
extern "C" void kernel_launch(void* const* d_in, const int* in_sizes, int n_in,
                              void* d_out, int out_size) {
    const float* dist  = (const float*)d_in[0];
    const float* angle = (const float*)d_in[1];
    const int*   idx   = (const int*)  d_in[2];
    float*       out   = (float*)      d_out;
    int T = in_sizes[1];

    setup_tab_kernel<<<NUM_SPH, 256>>>();

    int nBlk  = T / BT;                       // 32768
    int chunk = (nBlk + NCHUNK - 1) / NCHUNK; // 16384
    for (int c = 0; c < NCHUNK; ++c) {
        int off = c * chunk;
        int nb  = (off + chunk <= nBlk) ? chunk : (nBlk - off);
        if (nb > 0) out_kernel<<<nb, OTPB>>>(dist, angle, idx, out, off);
    }
}

// round 16
// speedup vs baseline: 1.4566x; 1.1440x over previous
#include <cuda_runtime.h>
#include <cuda_fp16.h>
#include <math.h>

#define NUM_SPH 7
#define NUM_RAD 6
#define NBASIS  (NUM_SPH * NUM_RAD)   // 42
#define MAX_E   524288

#define TABN    512                   // lerp intervals over x in [0.1, 1.0]
#define NREC    (NBASIS / 2)          // 21 packed records per row

#define BT      128                   // triplets per out-block
#define OTPB    224                   // 7 warps; 128*42/2 = 2688 = 12*224
#define NCHUNK  2

// root scan grid: x in [3.0, 3.0 + 0.02*1551 = 34.02]
#define SCAN_NP   1552
#define SCAN_LO   3.0f
#define SCAN_H    0.02f

// --------------------------------------------------------------------------
__device__ float g_zeros[NUM_SPH][NUM_RAD];
__device__ float g_norms[NUM_SPH][NUM_RAD];
// packed record per (row i, even j): half4 = (v_j, v_j+1, d_j, d_j+1), 8B.
// row stride = 21 records = 168B. total = 513*168B = 86KB -> L1-resident.
__device__ __align__(256) uint2 g_tabp[(size_t)(TABN + 1) * NREC];

// --------------------------------------------------------------------------
// fp32 spherical Bessel pair (j_l, j_{l-1}) via upward recurrence (z >= 3).
// --------------------------------------------------------------------------
__device__ __forceinline__ void jn_pair_f(int l, float z, float& f, float& fm) {
    float s, c;
    sincosf(z, &s, &c);
    float j0 = s / z;
    if (l == 0) { f = j0; fm = c / z; return; }      // j_{-1} = cos/z
    float j1 = s / (z * z) - c / z;
    float a = j0, b = j1;
    for (int i = 1; i < l; ++i) {
        float nx = (2.0f * i + 1.0f) / z * b - a;
        a = b; b = nx;
    }
    f = b; fm = a;
}

// --------------------------------------------------------------------------
// 1) roots: one block per l. fp32 scan -> brackets -> 5 fp32 Newton iters
//    (safeguarded) -> fp32 norms. No fp64 anywhere.
// --------------------------------------------------------------------------
__global__ void roots_kernel() {
    __shared__ unsigned char sg[SCAN_NP];
    __shared__ int cnt[256];
    __shared__ int brk[NUM_RAD];
    int l = blockIdx.x;
    int t = threadIdx.x;

    // ---- A: sign scan ----
    for (int p = t; p < SCAN_NP; p += 256) {
        float x = SCAN_LO + SCAN_H * (float)p;
        float v, vm;
        jn_pair_f(l, x, v, vm);
        sg[p] = (unsigned char)(v < 0.0f);
    }
    __syncthreads();

    // ---- B: brackets ----
    const int NI  = SCAN_NP - 1;
    const int per = (NI + 255) / 256;
    int i0 = t * per, i1 = i0 + per; if (i1 > NI) i1 = NI;

    int local = 0;
    for (int i = i0; i < i1; ++i) local += (sg[i] != sg[i + 1]);
    cnt[t] = local;
    __syncthreads();

    if (t == 0) {
        int run = 0;
        for (int j = 0; j < 256; ++j) { int c0 = cnt[j]; cnt[j] = run; run += c0; }
    }
    __syncthreads();

    int r = cnt[t];
    for (int i = i0; i < i1; ++i) {
        if (sg[i] != sg[i + 1]) {
            if (r < NUM_RAD) brk[r] = i;
            ++r;
        }
    }
    __syncthreads();

    // ---- C: Newton ----
    if (t < NUM_RAD) {
        int k = t;
        int i = brk[k];
        float lo = SCAN_LO + SCAN_H * (float)i - SCAN_H;   // expanded bracket
        float hi = lo + 3.0f * SCAN_H;
        float flo, fd;
        jn_pair_f(l, lo, flo, fd);

        float z = 0.5f * (lo + hi);
        #pragma unroll
        for (int it = 0; it < 5; ++it) {
            float f, fm;
            jn_pair_f(l, z, f, fm);
            if ((f < 0.0f) == (flo < 0.0f)) { lo = z; flo = f; } else { hi = z; }
            float fp = fm - ((float)(l + 1) / z) * f;
            float zn = z - f / fp;
            if (!(zn > lo && zn < hi)) zn = 0.5f * (lo + hi);
            z = zn;
        }

        float f7, fm7;
        jn_pair_f(l + 1, z, f7, fm7);
        g_zeros[l][k] = z;
        g_norms[l][k] = sqrtf(2.0f) / fabsf(f7);
    }
}

// --------------------------------------------------------------------------
// helper: fp32 reference recurrence, 6 radial values for (x, l)
// --------------------------------------------------------------------------
__device__ __forceinline__ void rbf_row(float x, int l,
                                        const float* zr, const float* nr,
                                        float* outv) {
    #pragma unroll
    for (int k = 0; k < NUM_RAD; ++k) {
        float z = x * zr[k];
        float s, c;
        sincosf(z, &s, &c);
        float j0 = s / z;
        float res = j0;
        if (l > 0) {
            float j1 = s / (z * z) - c / z;
            float jm = j0, jc = j1;
            for (int i = 1; i < l; ++i) {
                float jn = (2.0f * i + 1.0f) / z * jc - jm;
                jm = jc; jc = jn;
            }
            res = jc;
        }
        outv[k] = nr[k] * res;
    }
}

// --------------------------------------------------------------------------
// 2) Table-gen (point-parallel): one thread per (p, l); computes rbf at x_p
//    and x_{p+1}, packs (v, d) half4 records. 15 blocks -> fully parallel.
// --------------------------------------------------------------------------
__global__ void tab_kernel() {
    int gid = blockIdx.x * blockDim.x + threadIdx.x;
    if (gid >= (TABN + 1) * NUM_SPH) return;
    int l = gid % NUM_SPH;
    int p = gid / NUM_SPH;
    float x0 = 0.1f + (0.9f / TABN) * (float)p;
    float x1 = 0.1f + (0.9f / TABN) * (float)(p + 1);   // d unused for p==TABN

    float zr[NUM_RAD], nr[NUM_RAD];
    #pragma unroll
    for (int k = 0; k < NUM_RAD; ++k) { zr[k] = g_zeros[l][k]; nr[k] = g_norms[l][k]; }

    float v0[NUM_RAD], v1[NUM_RAD];
    rbf_row(x0, l, zr, nr, v0);
    rbf_row(x1, l, zr, nr, v1);

    uint2* row = g_tabp + (size_t)p * NREC + l * (NUM_RAD / 2);
    #pragma unroll
    for (int r = 0; r < NUM_RAD / 2; ++r) {
        __half2 vh = __floats2half2_rn(v0[2*r], v0[2*r+1]);
        __half2 dh = __floats2half2_rn(v1[2*r] - v0[2*r], v1[2*r+1] - v0[2*r+1]);
        uint2 rec;
        rec.x = *reinterpret_cast<unsigned*>(&vh);
        rec.y = *reinterpret_cast<unsigned*>(&dh);
        row[r] = rec;
    }
}

// --------------------------------------------------------------------------
// 3) FUSED out (best measured, R12/R15 float2 version): per float2 output =
//    1 scattered LDG.64 (packed half4 record, L1-resident 86KB table) + LDS +
//    dense STG.64 (evict-first).
// --------------------------------------------------------------------------
__global__ void __launch_bounds__(OTPB) out_kernel(
        const float* __restrict__ dist,
        const float* __restrict__ angle,
        const int*   __restrict__ idx_kj,
        float*       __restrict__ out,
        int blockOff) {
    __shared__ float scbf[BT][8];
    __shared__ float2 sif[BT];          // (row record-offset as int bits, lerp f)

    const float pref[NUM_SPH] = {
        0.28209479177387814f, 0.48860251190291992f, 0.63078313050504009f,
        0.74635266518023080f, 0.84628437532163443f, 0.93560257962738880f,
        1.01710723628205460f
    };

    int blk = blockIdx.x + blockOff;
    int tid = threadIdx.x;
    int t0  = blk * BT;

    // ---- 1a ----
    if (tid < BT) {
        int t = t0 + tid;
        int e = __ldg(&idx_kj[t]);
        float x = __ldg(&dist[e]) * 0.2f;
        float u = (x - 0.1f) * ((float)TABN / 0.9f);
        if (u < 0.0f) u = 0.0f;
        int i = (int)u;
        if (i > TABN - 1) i = TABN - 1;
        sif[tid] = make_float2(__int_as_float(i * NREC), u - (float)i);

        float ct = cosf(angle[t]);
        float pm = 1.0f, pc = ct;
        scbf[tid][0] = pref[0] * pm;
        scbf[tid][1] = pref[1] * pc;
        #pragma unroll
        for (int l = 2; l < NUM_SPH; ++l) {
            float pn = ((2.0f * l - 1.0f) * ct * pc - (l - 1.0f) * pm) / (float)l;
            pm = pc; pc = pn;
            scbf[tid][l] = pref[l] * pn;
        }
    }
    __syncthreads();

    // ---- 2 ----
    float2* o2 = reinterpret_cast<float2*>(out + (size_t)blk * (BT * NBASIS));

    #pragma unroll
    for (int it = 0; it < 12; ++it) {
        unsigned w  = it * OTPB + tid;          // 0..2687
        unsigned g  = 2u * w;                   // even
        unsigned tl = (g * 6242u) >> 18;        // g/42, exact for g<5376
        unsigned j  = g - tl * 42u;             // even, 0..40
        unsigned rj = j >> 1;                   // record index within row

        float2 rf = sif[tl];
        int    ro = __float_as_int(rf.x);       // i * NREC
        float  f  = rf.y;

        uint2 rec = __ldg(&g_tabp[ro + rj]);
        float2 v = __half22float2(*reinterpret_cast<__half2*>(&rec.x));
        float2 d = __half22float2(*reinterpret_cast<__half2*>(&rec.y));

        float c = scbf[tl][(j * 171u) >> 10];   // j/6

        float2 r;
        r.x = (v.x + f * d.x) * c;
        r.y = (v.y + f * d.y) * c;
        __stcs(&o2[w], r);
    }
}

// --------------------------------------------------------------------------
extern "C" void kernel_launch(void* const* d_in, const int* in_sizes, int n_in,
                              void* d_out, int out_size) {
    const float* dist  = (const float*)d_in[0];
    const float* angle = (const float*)d_in[1];
    const int*   idx   = (const int*)  d_in[2];
    float*       out   = (float*)      d_out;
    int T = in_sizes[1];

    roots_kernel<<<NUM_SPH, 256>>>();

    int nTab = (TABN + 1) * NUM_SPH;
    tab_kernel<<<(nTab + 255) / 256, 256>>>();

    int nBlk  = T / BT;                       // 32768
    int chunk = (nBlk + NCHUNK - 1) / NCHUNK; // 16384
    for (int c = 0; c < NCHUNK; ++c) {
        int off = c * chunk;
        int nb  = (off + chunk <= nBlk) ? chunk : (nBlk - off);
        if (nb > 0) out_kernel<<<nb, OTPB>>>(dist, angle, idx, out, off);
    }
}